// round 1
// baseline (speedup 1.0000x reference)
#include <cuda_runtime.h>
#include <cstdint>

// ============================================================================
// RobustNeuralKalmanFilter: B=8, S=4096, H=512
//   noise = softplus(lstm @ W^T + b)        -> (B*S=32768) x (2H=1024) GEMM
//   Kalman scan over s per (b,h) channel    -> 4096 channels x 4096 steps
// ============================================================================

static constexpr int B_ = 8;
static constexpr int S_ = 4096;
static constexpr int H_ = 512;
static constexpr int M_ = B_ * S_;   // 32768
static constexpr int N_ = 2 * H_;    // 1024
static constexpr int K_ = H_;        // 512

// Scratch for the softplus'd noise (Q in cols [0,512), R in cols [512,1024)).
__device__ float g_noise[(size_t)M_ * N_];   // 128 MB static device scratch

__device__ __forceinline__ float softplus_f(float x) {
    // max(x,0) + log1p(exp(-|x|))  == jax.nn.softplus, stable
    return fmaxf(x, 0.0f) + log1pf(__expf(-fabsf(x)));
}

// ---------------------------------------------------------------------------
// GEMM + softplus. C[m,n] = softplus( sum_k A[m,k]*W[n,k] + bias[n] )
// CTA tile 128x128, K-chunk 16, 256 threads, 8x8 per thread.
// Inner product uses packed fma.rn.f32x2 (2 fp32 FMA lanes / instr) to hit the
// full 128-lane fp32 rate on sm_103a (FFMA-3reg alone is half rate).
// ---------------------------------------------------------------------------
__global__ __launch_bounds__(256, 2)
void gemm_softplus_kernel(const float* __restrict__ A,
                          const float* __restrict__ W,
                          const float* __restrict__ bias)
{
    __shared__ __align__(16) float As[2][16][132];  // [k][m], padded ld=132
    __shared__ __align__(16) float Ws[2][16][132];  // [k][n]

    const int t  = threadIdx.x;
    const int n0 = blockIdx.x * 128;   // x = ntile so same-mtile CTAs are adjacent
    const int m0 = blockIdx.y * 128;

    // Loader mapping: thread -> (row lr in 0..63, k-quad lq in 0..3); each thread
    // loads rows lr and lr+64 of both A and W tiles (one float4 each).
    const int lr = t >> 2;
    const int lq = t & 3;

    const float* Ap = A + (size_t)(m0 + lr) * K_ + lq * 4;
    const float* Wp = W + (size_t)(n0 + lr) * K_ + lq * 4;

    // ---- prologue: stage K-chunk 0 ----
    {
        float4 a0 = *(const float4*)Ap;
        float4 a1 = *(const float4*)(Ap + (size_t)64 * K_);
        float4 w0 = *(const float4*)Wp;
        float4 w1 = *(const float4*)(Wp + (size_t)64 * K_);
        float va0[4] = {a0.x, a0.y, a0.z, a0.w};
        float va1[4] = {a1.x, a1.y, a1.z, a1.w};
        float vw0[4] = {w0.x, w0.y, w0.z, w0.w};
        float vw1[4] = {w1.x, w1.y, w1.z, w1.w};
#pragma unroll
        for (int c = 0; c < 4; c++) {
            As[0][lq * 4 + c][lr]      = va0[c];
            As[0][lq * 4 + c][lr + 64] = va1[c];
            Ws[0][lq * 4 + c][lr]      = vw0[c];
            Ws[0][lq * 4 + c][lr + 64] = vw1[c];
        }
    }
    __syncthreads();

    unsigned long long acc[8][4];
#pragma unroll
    for (int i = 0; i < 8; i++)
#pragma unroll
        for (int j = 0; j < 4; j++) acc[i][j] = 0ull;   // {0.f,0.f}

    const int ty = t >> 4;   // 0..15 -> m rows ty*8..ty*8+7
    const int tx = t & 15;   // 0..15 -> n cols tx*8..tx*8+7

    for (int kk = 0; kk < 32; ++kk) {
        // prefetch next K-chunk from global while computing current
        float4 na0, na1, nw0, nw1;
        if (kk < 31) {
            const float* ap = Ap + (kk + 1) * 16;
            const float* wp = Wp + (kk + 1) * 16;
            na0 = *(const float4*)ap;
            na1 = *(const float4*)(ap + (size_t)64 * K_);
            nw0 = *(const float4*)wp;
            nw1 = *(const float4*)(wp + (size_t)64 * K_);
        }

        const int cb = kk & 1;
#pragma unroll
        for (int k = 0; k < 16; k++) {
            float4 av0 = *(const float4*)&As[cb][k][ty * 8];
            float4 av1 = *(const float4*)&As[cb][k][ty * 8 + 4];
            ulonglong2 bv0 = *(const ulonglong2*)&Ws[cb][k][tx * 8];
            ulonglong2 bv1 = *(const ulonglong2*)&Ws[cb][k][tx * 8 + 4];
            float av[8] = {av0.x, av0.y, av0.z, av0.w,
                           av1.x, av1.y, av1.z, av1.w};
#pragma unroll
            for (int i = 0; i < 8; i++) {
                unsigned long long a2;
                asm("mov.b64 %0, {%1, %1};" : "=l"(a2) : "f"(av[i]));
                asm("fma.rn.f32x2 %0, %1, %2, %0;" : "+l"(acc[i][0]) : "l"(a2), "l"(bv0.x));
                asm("fma.rn.f32x2 %0, %1, %2, %0;" : "+l"(acc[i][1]) : "l"(a2), "l"(bv0.y));
                asm("fma.rn.f32x2 %0, %1, %2, %0;" : "+l"(acc[i][2]) : "l"(a2), "l"(bv1.x));
                asm("fma.rn.f32x2 %0, %1, %2, %0;" : "+l"(acc[i][3]) : "l"(a2), "l"(bv1.y));
            }
        }

        if (kk < 31) {
            const int nb = cb ^ 1;
            float va0[4] = {na0.x, na0.y, na0.z, na0.w};
            float va1[4] = {na1.x, na1.y, na1.z, na1.w};
            float vw0[4] = {nw0.x, nw0.y, nw0.z, nw0.w};
            float vw1[4] = {nw1.x, nw1.y, nw1.z, nw1.w};
#pragma unroll
            for (int c = 0; c < 4; c++) {
                As[nb][lq * 4 + c][lr]      = va0[c];
                As[nb][lq * 4 + c][lr + 64] = va1[c];
                Ws[nb][lq * 4 + c][lr]      = vw0[c];
                Ws[nb][lq * 4 + c][lr + 64] = vw1[c];
            }
        }
        __syncthreads();
    }

    // ---- epilogue: bias + softplus + store to g_noise ----
    const int nb = n0 + tx * 8;
    float bb[8];
#pragma unroll
    for (int j = 0; j < 8; j++) bb[j] = bias[nb + j];

#pragma unroll
    for (int i = 0; i < 8; i++) {
        const int m = m0 + ty * 8 + i;
        float o[8];
#pragma unroll
        for (int jp = 0; jp < 4; jp++) {
            unsigned long long v = acc[i][jp];
            float lo = __uint_as_float((unsigned)(v & 0xffffffffull));
            float hi = __uint_as_float((unsigned)(v >> 32));
            o[2 * jp]     = softplus_f(lo + bb[2 * jp]);
            o[2 * jp + 1] = softplus_f(hi + bb[2 * jp + 1]);
        }
        float* np_ = g_noise + (size_t)m * N_ + nb;
        *(float4*)np_       = make_float4(o[0], o[1], o[2], o[3]);
        *(float4*)(np_ + 4) = make_float4(o[4], o[5], o[6], o[7]);
    }
}

// ---------------------------------------------------------------------------
// Sequential Kalman scan, one thread per (b,h) channel (4096 threads).
// 16-step register double-buffer: prefetch distance 16*~36cyc ≈ DRAM latency.
// ---------------------------------------------------------------------------
__device__ __forceinline__ void load_chunk(const float* __restrict__ zp,
                                           const float* __restrict__ np,
                                           int base,
                                           float (&Z)[16], float (&Q)[16], float (&R)[16])
{
#pragma unroll
    for (int i = 0; i < 16; i++) {
        const size_t s = (size_t)(base + i);
        Z[i] = zp[s * H_];
        Q[i] = np[s * N_];
        R[i] = np[s * N_ + H_] + 1e-6f;   // fold the +eps into the load shadow
    }
}

__global__ void kalman_scan_kernel(const float* __restrict__ z,
                                   float* __restrict__ out)
{
    const int t = blockIdx.x * blockDim.x + threadIdx.x;   // 0..4095
    const int b = t >> 9;          // /512
    const int h = t & (H_ - 1);

    const float* zp = z       + (size_t)b * S_ * H_ + h;
    const float* np = g_noise + (size_t)b * S_ * N_ + h;
    float*       op = out     + (size_t)b * S_ * H_ + h;

    float ZA[16], QA[16], RA[16], ZB[16], QB[16], RB[16];

    load_chunk(zp, np, 0, ZA, QA, RA);
    float state = ZA[0];   // state0 = lstm_out[:,0,:]; step s=0 is a no-op on state
    float P = 0.1f;

    for (int c = 0; c < 256; c += 2) {
        load_chunk(zp, np, (c + 1) * 16, ZB, QB, RB);
#pragma unroll
        for (int i = 0; i < 16; i++) {
            const float Pp = P + QA[i];
            const float K  = __fdividef(Pp, Pp + RA[i]);
            state = fmaf(K, ZA[i] - state, state);
            P = (1.0f - K) * Pp;
            op[(size_t)(c * 16 + i) * H_] = state;
        }
        if (c + 2 < 256) load_chunk(zp, np, (c + 2) * 16, ZA, QA, RA);
#pragma unroll
        for (int i = 0; i < 16; i++) {
            const float Pp = P + QB[i];
            const float K  = __fdividef(Pp, Pp + RB[i]);
            state = fmaf(K, ZB[i] - state, state);
            P = (1.0f - K) * Pp;
            op[(size_t)((c + 1) * 16 + i) * H_] = state;
        }
    }
}

// ---------------------------------------------------------------------------
extern "C" void kernel_launch(void* const* d_in, const int* in_sizes, int n_in,
                              void* d_out, int out_size)
{
    const float* lstm = (const float*)d_in[0];   // (8,4096,512) f32
    const float* W    = (const float*)d_in[1];   // (1024,512)   f32
    const float* bias = (const float*)d_in[2];   // (1024,)      f32
    float*       out  = (float*)d_out;           // (8,4096,512) f32

    // GEMM+softplus: grid.x over N tiles (8) so same-M CTAs run together
    // (A tile hits L2 for all 8 N-tiles; W (2MB) is fully L2-resident).
    gemm_softplus_kernel<<<dim3(8, 256), 256>>>(lstm, W, bias);

    // Scan: 4096 channels, 1 thread each; 1 warp per block to spread across SMs.
    kalman_scan_kernel<<<128, 32>>>(lstm, out);
}